// round 13
// baseline (speedup 1.0000x reference)
#include <cuda_runtime.h>
#include <cuda_bf16.h>
#include <math.h>
#include <cstdint>

// ---------------- problem constants ----------------
#define BB       256
#define DMODEL   2048
#define DINNER   8192
#define DSTATE   16
#define DTRANK   128
#define XPN      (DTRANK + 2*DSTATE)   // 160

// ---------------- scratch (device globals; no allocation) ----------------
__device__ float g_xz [BB * 2 * DINNER];   // xi | z
__device__ float g_xc [BB * DINNER];
__device__ float g_xdb[BB * XPN];
__device__ float g_dt [BB * DINNER];
__device__ float g_A  [DINNER * DSTATE];

// bf16 hi/lo split tensors (A-operands only; tiny)
__device__ __nv_bfloat16 g_xhi  [BB * DMODEL];
__device__ __nv_bfloat16 g_xlo  [BB * DMODEL];
__device__ __nv_bfloat16 g_yhi  [BB * DINNER];
__device__ __nv_bfloat16 g_ylo  [BB * DINNER];

// ---------------- helpers ----------------
__device__ __forceinline__ uint32_t smem_u32(const void* p) {
    uint32_t a;
    asm("{ .reg .u64 t; cvta.to.shared.u64 t, %1; cvt.u32.u64 %0, t; }" : "=r"(a) : "l"(p));
    return a;
}

__device__ __forceinline__ void ldmx4(uint32_t* r, uint32_t addr) {
    asm volatile("ldmatrix.sync.aligned.m8n8.x4.shared.b16 {%0,%1,%2,%3}, [%4];"
        : "=r"(r[0]), "=r"(r[1]), "=r"(r[2]), "=r"(r[3]) : "r"(addr));
}

__device__ __forceinline__ void mma16816(float* d, const uint32_t* a,
                                         uint32_t b0, uint32_t b1) {
    asm volatile(
        "mma.sync.aligned.m16n8k16.row.col.f32.bf16.bf16.f32 "
        "{%0,%1,%2,%3}, {%4,%5,%6,%7}, {%8,%9}, {%0,%1,%2,%3};"
        : "+f"(d[0]), "+f"(d[1]), "+f"(d[2]), "+f"(d[3])
        : "r"(a[0]), "r"(a[1]), "r"(a[2]), "r"(a[3]), "r"(b0), "r"(b1));
}

__device__ __forceinline__ void cp16(uint32_t s, const void* g) {
    asm volatile("cp.async.cg.shared.global [%0], [%1], 16;" :: "r"(s), "l"(g));
}
#define CP_COMMIT() asm volatile("cp.async.commit_group;" ::: "memory")
#define CP_WAIT(n)  asm volatile("cp.async.wait_group %0;" :: "n"(n) : "memory")

#define STS128(addr, r) \
    asm volatile("st.shared.v4.b32 [%0], {%1,%2,%3,%4};" \
        :: "r"(addr), "r"((r)[0]), "r"((r)[1]), "r"((r)[2]), "r"((r)[3]) : "memory")

// fp32 pair -> bf16x2 hi (truncation via PRMT) + bf16x2 lo (residual, RN)
__device__ __forceinline__ void cvt_pair(float2 v, uint32_t& hi, uint32_t& lo) {
    uint32_t ax = __float_as_uint(v.x), ay = __float_as_uint(v.y);
    uint32_t h;
    asm("prmt.b32 %0, %1, %2, 0x7632;" : "=r"(h) : "r"(ax), "r"(ay));
    float hx = __uint_as_float(ax & 0xFFFF0000u);
    float hy = __uint_as_float(ay & 0xFFFF0000u);
    __nv_bfloat162 l = __floats2bfloat162_rn(v.x - hx, v.y - hy);
    hi = h;
    lo = *(uint32_t*)&l;
}

// ---------------- HMMA bf16 hi/lo GEMM ----------------
// C[M,N] (+)= (Ah+Al)[M,K] * Bf[N,K]^T. 3-product compensation.
// 256 threads, tile 128x128x32.
// A: cp.async, 3 stages x 16 KB (hi 8K + lo 8K), 64 B rows, swizzle c^((r>>1)&3).
// Bf: cp.async fp32, 2 stages x 16 KB, 128 B rows, swizzle c^(r&7).
// Bb: bf16 hi/lo, 2 buffers x 16 KB, layout identical to A stages.
// Each iter: convert Bf(it+1)->Bb (fire-and-forget, consumed after next barrier)
// while computing pure LDSM+MMA from Bb(it). Commit order Bf-then-A so
// CP_WAIT(1) guarantees Bf(it+1) resident while A(it+1) still prefetches.
// One __syncthreads per iteration. Total smem 112 KB -> 2 CTAs/SM.
// EPI: 0 = store, 1 = atomicAdd (split-K). iters must be >= 3.
#define GBM 128
#define GBN 128
#define GBK 32
#define A_STG_B   16384
#define BF_BASE   49152
#define BF_STG_B  16384
#define BB_BASE   81920
#define BB_STG_B  16384
#define HSM_TOT   114688

template<int EPI, int SPLITK>
__global__ void __launch_bounds__(256, 2)
hmma_gemm(const __nv_bfloat16* __restrict__ Ah, const __nv_bfloat16* __restrict__ Al,
          const float* __restrict__ Bf,
          float* __restrict__ C, int ldc, int K)
{
    extern __shared__ char smraw[];

    const int tid = threadIdx.x;
    const int n0  = blockIdx.x * GBN;
    const int m0  = blockIdx.y * GBM;
    const int kChunk = K / SPLITK;
    const int kb  = blockIdx.z * kChunk;
    const int iters = kChunk / GBK;

    const uint32_t usm = smem_u32(smraw);

    auto issueA = [&](int stg, int koff) {
        uint32_t sbase = usm + (uint32_t)stg * A_STG_B;
        #pragma unroll
        for (int u = 0; u < 2; u++) {
            int idx = u * 256 + tid;
            int r   = idx >> 2;
            int c   = idx & 3;
            size_t ga   = (size_t)(m0 + r) * K + koff + c * 8;
            uint32_t so = (uint32_t)(r * 64 + ((c ^ ((r >> 1) & 3)) * 16));
            cp16(sbase + so, Ah + ga);
            cp16(sbase + 8192 + so, Al + ga);
        }
    };
    auto issueBf = [&](int stg, int koff) {
        uint32_t sbase = usm + BF_BASE + (uint32_t)stg * BF_STG_B;
        #pragma unroll
        for (int u = 0; u < 4; u++) {
            int idx = u * 256 + tid;
            int r   = idx >> 3;
            int c   = idx & 7;
            size_t gb   = (size_t)(n0 + r) * K + koff + c * 4;
            uint32_t so = (uint32_t)(r * 128 + ((c ^ (r & 7)) * 16));
            cp16(sbase + so, Bf + gb);
        }
    };

    // conversion mapping: thread -> (row, k-half of 16)
    const int cr  = tid >> 1;
    const int chh = tid & 1;
    auto convertB = [&](int bfs, int bbs) {
        uint32_t fb = usm + BF_BASE + (uint32_t)bfs * BF_STG_B;
        uint32_t bb = usm + BB_BASE + (uint32_t)bbs * BB_STG_B;
        float f[16];
        #pragma unroll
        for (int j = 0; j < 4; j++) {
            int c = chh * 4 + j;
            uint32_t a = fb + (uint32_t)(cr * 128 + ((c ^ (cr & 7)) * 16));
            float4 v;
            asm volatile("ld.shared.v4.f32 {%0,%1,%2,%3}, [%4];"
                : "=f"(v.x), "=f"(v.y), "=f"(v.z), "=f"(v.w) : "r"(a));
            f[j*4+0] = v.x; f[j*4+1] = v.y; f[j*4+2] = v.z; f[j*4+3] = v.w;
        }
        uint32_t hi[8], lo[8];
        #pragma unroll
        for (int j = 0; j < 8; j++)
            cvt_pair(make_float2(f[2*j], f[2*j+1]), hi[j], lo[j]);
        #pragma unroll
        for (int q = 0; q < 2; q++) {
            int c2 = chh * 2 + q;
            uint32_t off = (uint32_t)(cr * 64 + ((c2 ^ ((cr >> 1) & 3)) * 16));
            STS128(bb + off, (hi + q*4));
            STS128(bb + 8192 + off, (lo + q*4));
        }
    };

    // ---- prologue ----
    issueBf(0, kb);        CP_COMMIT();
    issueA (0, kb);        CP_COMMIT();
    issueBf(1, kb + GBK);  CP_COMMIT();
    issueA (1, kb + GBK);  CP_COMMIT();
    CP_WAIT(1);            // Bf0, A0, Bf1 done (A1 may pend)
    __syncthreads();
    convertB(0, 0);        // Bb(0)

    // compute mapping: 2m x 4n warps, warp tile 64x32
    const int w    = tid >> 5;
    const int lane = tid & 31;
    const int wm   = (w & 1) * 64;
    const int wn   = (w >> 1) * 32;
    const int g    = lane >> 3;
    const int rr   = lane & 7;

    float acc[4][4][4];
    #pragma unroll
    for (int i = 0; i < 4; i++)
        #pragma unroll
        for (int j = 0; j < 4; j++)
            #pragma unroll
            for (int c = 0; c < 4; c++) acc[i][j][c] = 0.0f;

    for (int it = 0; it < iters; ++it) {
        CP_WAIT(1);              // FIFO: Bf(it+1) complete, A(it+1) may pend
        __syncthreads();         // Bb(it) STS visible; prior compute drained

        if (it + 2 < iters) issueBf((it + 2) & 1, kb + (it + 2) * GBK);
        CP_COMMIT();
        if (it + 2 < iters) issueA((it + 2) % 3, kb + (it + 2) * GBK);
        CP_COMMIT();

        if (it + 1 < iters) convertB((it + 1) & 1, (it + 1) & 1);

        const uint32_t uAh = usm + (uint32_t)(it % 3) * A_STG_B;
        const uint32_t uAl = uAh + 8192;
        const uint32_t uBh = usm + BB_BASE + (uint32_t)(it & 1) * BB_STG_B;
        const uint32_t uBl = uBh + 8192;

        #pragma unroll
        for (int ks = 0; ks < 2; ks++) {
            const int cc = ks * 2 + (g >> 1);    // 16B chunk within 64B row

            uint32_t bh[4][2], bl[4][2];
            #pragma unroll
            for (int pi = 0; pi < 2; pi++) {
                int brow = wn + pi * 16 + (g & 1) * 8 + rr;
                uint32_t off = (uint32_t)(brow * 64 + ((cc ^ ((brow >> 1) & 3)) * 16));
                uint32_t t[4];
                ldmx4(t, uBh + off);
                bh[pi*2+0][0] = t[0]; bh[pi*2+0][1] = t[2];
                bh[pi*2+1][0] = t[1]; bh[pi*2+1][1] = t[3];
                ldmx4(t, uBl + off);
                bl[pi*2+0][0] = t[0]; bl[pi*2+0][1] = t[2];
                bl[pi*2+1][0] = t[1]; bl[pi*2+1][1] = t[3];
            }
            #pragma unroll
            for (int mi = 0; mi < 4; mi++) {
                int arow = wm + mi * 16 + (g & 1) * 8 + rr;
                uint32_t off = (uint32_t)(arow * 64 + ((cc ^ ((arow >> 1) & 3)) * 16));
                uint32_t ah[4], al[4];
                ldmx4(ah, uAh + off);
                ldmx4(al, uAl + off);
                #pragma unroll
                for (int ni = 0; ni < 4; ni++) {
                    mma16816(acc[mi][ni], ah, bh[ni][0], bh[ni][1]);
                    mma16816(acc[mi][ni], al, bh[ni][0], bh[ni][1]);
                    mma16816(acc[mi][ni], ah, bl[ni][0], bl[ni][1]);
                }
            }
        }
    }

    // ---- epilogue ----
    const int erow = lane >> 2;
    const int ecol = (lane & 3) * 2;
    #pragma unroll
    for (int mi = 0; mi < 4; mi++) {
        #pragma unroll
        for (int ni = 0; ni < 4; ni++) {
            int r0 = m0 + wm + mi * 16 + erow;
            int c0 = n0 + wn + ni * 8 + ecol;
            float* p0 = C + (size_t)r0 * ldc + c0;
            float* p1 = C + (size_t)(r0 + 8) * ldc + c0;
            if (EPI == 0) {
                *(float2*)p0 = make_float2(acc[mi][ni][0], acc[mi][ni][1]);
                *(float2*)p1 = make_float2(acc[mi][ni][2], acc[mi][ni][3]);
            } else {
                atomicAdd(p0,     acc[mi][ni][0]);
                atomicAdd(p0 + 1, acc[mi][ni][1]);
                atomicAdd(p1,     acc[mi][ni][2]);
                atomicAdd(p1 + 1, acc[mi][ni][3]);
            }
        }
    }
}

// ---------------- small helpers ----------------
__global__ void zero_kernel(float* __restrict__ p, int n) {
    int i = blockIdx.x * blockDim.x + threadIdx.x;
    if (i < n) p[i] = 0.0f;
}

__global__ void precompute_A_kernel(const float* __restrict__ A_log) {
    int i = blockIdx.x * blockDim.x + threadIdx.x;
    if (i < DINNER * DSTATE) g_A[i] = -expf(A_log[i]);
}

// split fp32 -> bf16 hi + bf16 lo (residual), float4-vectorized (A operands only)
__global__ void split_bf16_kernel(const float4* __restrict__ in,
                                  __nv_bfloat162* __restrict__ hi,
                                  __nv_bfloat162* __restrict__ lo, int n4) {
    int i = blockIdx.x * blockDim.x + threadIdx.x;
    if (i >= n4) return;
    float4 v = in[i];
    __nv_bfloat162 h01 = __floats2bfloat162_rn(v.x, v.y);
    __nv_bfloat162 h23 = __floats2bfloat162_rn(v.z, v.w);
    float lx = v.x - __bfloat162float(h01.x);
    float ly = v.y - __bfloat162float(h01.y);
    float lz = v.z - __bfloat162float(h23.x);
    float lw = v.w - __bfloat162float(h23.y);
    hi[2*i]   = h01;
    hi[2*i+1] = h23;
    lo[2*i]   = __floats2bfloat162_rn(lx, ly);
    lo[2*i+1] = __floats2bfloat162_rn(lz, lw);
}

// ---------------- fp32 tiled SGEMM (small GEMMs) ----------------
template<int BM, int BN, int BK, int TM, int TN, int EPI>
__global__ void __launch_bounds__((BM/TM)*(BN/TN))
sgemm_nt(const float* __restrict__ A, int lda,
         const float* __restrict__ Bm, int ldb,
         float* __restrict__ C, int ldc,
         int M, int N, int K, int kChunk,
         const float* __restrict__ bias)
{
    constexpr int THREADS = (BM/TM)*(BN/TN);
    constexpr int KQ = BK / 4;
    constexpr int A4 = BM * BK / 4;
    constexpr int B4 = BN * BK / 4;

    __shared__ float As[BK][BM];
    __shared__ float Bs[BK][BN];

    const int tid = threadIdx.x;
    const int n0  = blockIdx.x * BN;
    const int m0  = blockIdx.y * BM;
    const int kb  = blockIdx.z * kChunk;
    const int ke  = (kb + kChunk < K) ? (kb + kChunk) : K;

    const int tc = tid % (BN / TN);
    const int tr = tid / (BN / TN);

    float acc[TM][TN];
    #pragma unroll
    for (int i = 0; i < TM; i++)
        #pragma unroll
        for (int j = 0; j < TN; j++) acc[i][j] = 0.0f;

    for (int k0 = kb; k0 < ke; k0 += BK) {
        #pragma unroll
        for (int i = tid; i < A4; i += THREADS) {
            int m  = i / KQ;
            int kq = i % KQ;
            float4 v = *(const float4*)&A[(size_t)(m0 + m) * lda + k0 + kq * 4];
            As[kq*4+0][m] = v.x; As[kq*4+1][m] = v.y;
            As[kq*4+2][m] = v.z; As[kq*4+3][m] = v.w;
        }
        #pragma unroll
        for (int i = tid; i < B4; i += THREADS) {
            int n  = i / KQ;
            int kq = i % KQ;
            float4 v = *(const float4*)&Bm[(size_t)(n0 + n) * ldb + k0 + kq * 4];
            Bs[kq*4+0][n] = v.x; Bs[kq*4+1][n] = v.y;
            Bs[kq*4+2][n] = v.z; Bs[kq*4+3][n] = v.w;
        }
        __syncthreads();

        #pragma unroll
        for (int kk = 0; kk < BK; kk++) {
            float a[TM], b[TN];
            #pragma unroll
            for (int i = 0; i < TM; i++) a[i] = As[kk][tr*TM + i];
            #pragma unroll
            for (int j = 0; j < TN; j++) b[j] = Bs[kk][tc*TN + j];
            #pragma unroll
            for (int i = 0; i < TM; i++)
                #pragma unroll
                for (int j = 0; j < TN; j++)
                    acc[i][j] = fmaf(a[i], b[j], acc[i][j]);
        }
        __syncthreads();
    }

    #pragma unroll
    for (int i = 0; i < TM; i++) {
        int m = m0 + tr*TM + i;
        #pragma unroll
        for (int j = 0; j < TN; j++) {
            int n = n0 + tc*TN + j;
            float v = acc[i][j];
            if (EPI == 0) {
                C[(size_t)m * ldc + n] = v;
            } else if (EPI == 1) {
                atomicAdd(&C[(size_t)m * ldc + n], v);
            } else {
                float x = v + bias[n];
                float r2 = fmaxf(x, 0.0f) + log1pf(__expf(-fabsf(x)));
                C[(size_t)m * ldc + n] = r2;
            }
        }
    }
}

// ---------------- conv window shift + SiLU ----------------
__global__ void conv_kernel(const float* __restrict__ cs_in,
                            const float* __restrict__ conv_w,
                            const float* __restrict__ conv_b,
                            float* __restrict__ cs_out)
{
    int idx = blockIdx.x * blockDim.x + threadIdx.x;
    int b = idx >> 13;
    int d = idx & (DINNER - 1);
    float4 cs = ((const float4*)cs_in)[idx];
    float4 w  = ((const float4*)conv_w)[d];
    float xi  = g_xz[(size_t)b * (2*DINNER) + d];
    float s = cs.y*w.x + cs.z*w.y + cs.w*w.z + xi*w.w + conv_b[d];
    float sig = 1.0f / (1.0f + __expf(-s));
    g_xc[idx] = s * sig;
    ((float4*)cs_out)[idx] = make_float4(cs.y, cs.z, cs.w, xi);
}

// ---------------- SSM state update + y (emits y as bf16 hi/lo) --------------
__global__ void ssm_kernel(const float* __restrict__ ssm_in,
                           const float* __restrict__ D_param,
                           float* __restrict__ ssm_out)
{
    __shared__ float bm[DSTATE], cm[DSTATE];
    const int b = blockIdx.y;
    const int d = blockIdx.x * blockDim.x + threadIdx.x;
    if (threadIdx.x < 2*DSTATE) {
        float v = g_xdb[b * XPN + DTRANK + threadIdx.x];
        if (threadIdx.x < DSTATE) bm[threadIdx.x] = v;
        else                      cm[threadIdx.x - DSTATE] = v;
    }
    __syncthreads();

    const int bd = b * DINNER + d;
    const float dtv = g_dt[bd];
    const float xcv = g_xc[bd];
    const float xdt = xcv * dtv;
    const size_t base = (size_t)bd * DSTATE;

    float yacc = 0.0f;
    #pragma unroll
    for (int n = 0; n < DSTATE; n += 4) {
        float4 a  = *(const float4*)&g_A[d * DSTATE + n];
        float4 st = *(const float4*)&ssm_in[base + n];
        float4 ns;
        ns.x = st.x * __expf(a.x * dtv) + xdt * bm[n+0];
        ns.y = st.y * __expf(a.y * dtv) + xdt * bm[n+1];
        ns.z = st.z * __expf(a.z * dtv) + xdt * bm[n+2];
        ns.w = st.w * __expf(a.w * dtv) + xdt * bm[n+3];
        yacc += ns.x * cm[n+0] + ns.y * cm[n+1] + ns.z * cm[n+2] + ns.w * cm[n+3];
        *(float4*)&ssm_out[base + n] = ns;
    }
    yacc += D_param[d] * xcv;
    float zv = g_xz[(size_t)b * (2*DINNER) + DINNER + d];
    yacc *= zv / (1.0f + __expf(-zv));

    __nv_bfloat16 h = __float2bfloat16(yacc);
    g_yhi[bd] = h;
    g_ylo[bd] = __float2bfloat16(yacc - __bfloat162float(h));
}

// ---------------- launch ----------------
extern "C" void kernel_launch(void* const* d_in, const int* in_sizes, int n_in,
                              void* d_out, int out_size)
{
    const float* x       = (const float*)d_in[0];
    const float* cs_in   = (const float*)d_in[1];
    const float* ssm_in  = (const float*)d_in[2];
    const float* W_in    = (const float*)d_in[3];
    const float* conv_w  = (const float*)d_in[4];
    const float* conv_b  = (const float*)d_in[5];
    const float* W_xproj = (const float*)d_in[6];
    const float* W_dt    = (const float*)d_in[7];
    const float* b_dt    = (const float*)d_in[8];
    const float* A_log   = (const float*)d_in[9];
    const float* D_param = (const float*)d_in[10];
    const float* W_out   = (const float*)d_in[11];

    float* out     = (float*)d_out;
    float* cs_out  = out + (size_t)BB * DMODEL;
    float* ssm_out = cs_out + (size_t)BB * DINNER * 4;

    void *p_xz, *p_xc, *p_xdb, *p_dt, *p_xhi, *p_xlo, *p_yhi, *p_ylo;
    cudaGetSymbolAddress(&p_xz,  g_xz);
    cudaGetSymbolAddress(&p_xc,  g_xc);
    cudaGetSymbolAddress(&p_xdb, g_xdb);
    cudaGetSymbolAddress(&p_dt,  g_dt);
    cudaGetSymbolAddress(&p_xhi, g_xhi);
    cudaGetSymbolAddress(&p_xlo, g_xlo);
    cudaGetSymbolAddress(&p_yhi, g_yhi);
    cudaGetSymbolAddress(&p_ylo, g_ylo);

    cudaFuncSetAttribute(hmma_gemm<0,1>, cudaFuncAttributeMaxDynamicSharedMemorySize, HSM_TOT);
    cudaFuncSetAttribute(hmma_gemm<1,8>, cudaFuncAttributeMaxDynamicSharedMemorySize, HSM_TOT);

    // launches 0-2, then GEMM1 as the 4th launch (ncu window profiles index 3)
    zero_kernel<<<(BB*XPN + 255)/256, 256>>>((float*)p_xdb, BB*XPN);
    zero_kernel<<<(BB*DMODEL + 255)/256, 256>>>(out, BB*DMODEL);
    split_bf16_kernel<<<(BB*DMODEL/4 + 255)/256, 256>>>(
        (const float4*)x, (__nv_bfloat162*)p_xhi, (__nv_bfloat162*)p_xlo, BB*DMODEL/4);

    // GEMM1: xz[256,16384] = x @ W_in^T   (B = W_in fp32, pipelined conversion)
    hmma_gemm<0,1><<<dim3((2*DINNER)/GBN, BB/GBM, 1), 256, HSM_TOT>>>(
        (const __nv_bfloat16*)p_xhi, (const __nv_bfloat16*)p_xlo,
        W_in, (float*)p_xz, 2*DINNER, DMODEL);

    precompute_A_kernel<<<(DINNER*DSTATE + 255)/256, 256>>>(A_log);

    // conv + SiLU
    conv_kernel<<<(BB*DINNER)/256, 256>>>(cs_in, conv_w, conv_b, cs_out);

    // GEMM3: x_db[256,160] = xc @ W_xproj^T  (fp32, BK=32, split-K=16, atomic)
    sgemm_nt<64,32,32,4,4,1><<<dim3(XPN/32, BB/64, 16), 128>>>(
        (const float*)p_xc, DINNER, W_xproj, DINNER, (float*)p_xdb, XPN,
        BB, XPN, DINNER, DINNER/16, nullptr);

    // GEMM4: dt[256,8192] = softplus(x_db[:, :128] @ W_dt^T + b_dt)  (fp32, BK=32)
    sgemm_nt<64,64,32,4,4,2><<<dim3(DINNER/64, BB/64, 1), 256>>>(
        (const float*)p_xdb, XPN, W_dt, DTRANK, (float*)p_dt, DINNER,
        BB, DINNER, DTRANK, DTRANK, b_dt);

    // SSM update + y (emits yhi/ylo)
    ssm_kernel<<<dim3(DINNER/256, BB), 256>>>(ssm_in, D_param, ssm_out);

    // GEMM6: out[256,2048] = y @ W_out^T  (split-K=8 -> 256 CTAs = 2/SM, atomic)
    hmma_gemm<1,8><<<dim3(DMODEL/GBN, BB/GBM, 8), 256, HSM_TOT>>>(
        (const __nv_bfloat16*)p_yhi, (const __nv_bfloat16*)p_ylo,
        W_out, out, DMODEL, DINNER);
}

// round 14
// speedup vs baseline: 1.2888x; 1.2888x over previous
#include <cuda_runtime.h>
#include <cuda_bf16.h>
#include <math.h>
#include <cstdint>

// ---------------- problem constants ----------------
#define BB       256
#define DMODEL   2048
#define DINNER   8192
#define DSTATE   16
#define DTRANK   128
#define XPN      (DTRANK + 2*DSTATE)   // 160

// ---------------- scratch (device globals; no allocation) ----------------
__device__ float g_xz [BB * 2 * DINNER];   // xi | z
__device__ float g_xc [BB * DINNER];
__device__ float g_xdb[BB * XPN];
__device__ float g_dt [BB * DINNER];
__device__ float g_A  [DINNER * DSTATE];
__device__ float g_xt [BB * DMODEL];       // x rounded to tf32
__device__ float g_y  [BB * DINNER];       // y rounded to tf32

// ---------------- helpers ----------------
__device__ __forceinline__ uint32_t smem_u32(const void* p) {
    uint32_t a;
    asm("{ .reg .u64 t; cvta.to.shared.u64 t, %1; cvt.u32.u64 %0, t; }" : "=r"(a) : "l"(p));
    return a;
}

__device__ __forceinline__ uint32_t f2tf32(float f) {
    uint32_t r;
    asm("cvt.rna.tf32.f32 %0, %1;" : "=r"(r) : "f"(f));
    return r;
}

__device__ __forceinline__ void mma_tf32(float* d, const uint32_t* a,
                                         uint32_t b0, uint32_t b1) {
    asm volatile(
        "mma.sync.aligned.m16n8k8.row.col.f32.tf32.tf32.f32 "
        "{%0,%1,%2,%3}, {%4,%5,%6,%7}, {%8,%9}, {%0,%1,%2,%3};"
        : "+f"(d[0]), "+f"(d[1]), "+f"(d[2]), "+f"(d[3])
        : "r"(a[0]), "r"(a[1]), "r"(a[2]), "r"(a[3]), "r"(b0), "r"(b1));
}

__device__ __forceinline__ void cp16(uint32_t s, const void* g) {
    asm volatile("cp.async.cg.shared.global [%0], [%1], 16;" :: "r"(s), "l"(g));
}
#define CP_COMMIT() asm volatile("cp.async.commit_group;" ::: "memory")
#define CP_WAIT(n)  asm volatile("cp.async.wait_group %0;" :: "n"(n) : "memory")

// ---------------- TF32 single-product GEMM ----------------
// C[M,N] (+)= A[M,K] * B[N,K]^T.  A pre-rounded to tf32 (fp32 storage);
// B raw fp32, cvt.rna at fragment load. m16n8k8 tf32 MMA.
// 256 threads, tile 128x128x32, 3-stage cp.async (32 KB/stage: A 16K + B 16K)
// -> 96 KB, 2 CTAs/SM. Single __syncthreads per iter (R12 schedule).
// Smem layout (both operands): 128 rows x 128 B (32 fp32); 16B-chunk swizzle
// chunk' = chunk ^ (row & 7)  -> conflict-free for the 8row x 4col lane pattern.
// EPI: 0 = store, 1 = atomicAdd (split-K). iters must be >= 3.
#define GBM 128
#define GBN 128
#define GBK 32
#define A_OFF 0
#define B_OFF 16384
#define STG_BYTES 32768
#define NSTAGE 3

template<int EPI, int SPLITK>
__global__ void __launch_bounds__(256, 2)
tf32_gemm(const float* __restrict__ Af, const float* __restrict__ Bf,
          float* __restrict__ C, int ldc, int K)
{
    extern __shared__ char smraw[];

    const int tid = threadIdx.x;
    const int n0  = blockIdx.x * GBN;
    const int m0  = blockIdx.y * GBM;
    const int kChunk = K / SPLITK;
    const int kb  = blockIdx.z * kChunk;
    const int iters = kChunk / GBK;

    const uint32_t usm = smem_u32(smraw);

    auto issue = [&](uint32_t sbase, int koff) {
        #pragma unroll
        for (int u = 0; u < 4; u++) {
            int idx = u * 256 + tid;
            int r   = idx >> 3;
            int c   = idx & 7;
            uint32_t so = (uint32_t)(r * 128 + ((c ^ (r & 7)) * 16));
            cp16(sbase + A_OFF + so, Af + (size_t)(m0 + r) * K + koff + c * 4);
            cp16(sbase + B_OFF + so, Bf + (size_t)(n0 + r) * K + koff + c * 4);
        }
    };

    // prologue: 2 stages in flight
    issue(usm, kb);                   CP_COMMIT();
    issue(usm + STG_BYTES, kb + GBK); CP_COMMIT();

    // warp mapping: 2m x 4n, warp tile 64x32
    const int w    = tid >> 5;
    const int lane = tid & 31;
    const int wm   = (w & 1) * 64;
    const int wn   = (w >> 1) * 32;
    const int grp  = lane >> 2;       // 0..7
    const int tg   = lane & 3;        // 0..3

    float acc[4][4][4];
    #pragma unroll
    for (int i = 0; i < 4; i++)
        #pragma unroll
        for (int j = 0; j < 4; j++)
            #pragma unroll
            for (int c = 0; c < 4; c++) acc[i][j][c] = 0.0f;

    int s = 0;
    for (int it = 0; it < iters; ++it) {
        CP_WAIT(1);              // stage s resident
        __syncthreads();         // + all warps done reading stage (it-1)

        if (it + 2 < iters) {
            int s2 = s + 2; if (s2 >= NSTAGE) s2 -= NSTAGE;
            issue(usm + (uint32_t)s2 * STG_BYTES, kb + (it + 2) * GBK);
        }
        CP_COMMIT();

        const char* stg = smraw + (uint32_t)s * STG_BYTES;
        const char* sA  = stg + A_OFF;
        const char* sB  = stg + B_OFF;

        #pragma unroll
        for (int ks = 0; ks < 4; ks++) {
            const int c0 = ks * 2;       // chunk of k = ks*8 + [0..3]
            const int c1 = ks * 2 + 1;   // chunk of k = ks*8 + [4..7]

            // ---- B fragments (4 n8 tiles), cvt.rna to tf32 ----
            uint32_t bfr[4][2];
            #pragma unroll
            for (int ni = 0; ni < 4; ni++) {
                int br = wn + ni * 8 + grp;
                const char* rowp = sB + br * 128 + tg * 4;
                float v0 = *(const float*)(rowp + ((c0 ^ (br & 7)) * 16));
                float v1 = *(const float*)(rowp + ((c1 ^ (br & 7)) * 16));
                bfr[ni][0] = f2tf32(v0);
                bfr[ni][1] = f2tf32(v1);
            }
            // ---- A fragments (pre-rounded) + MMAs ----
            #pragma unroll
            for (int mi = 0; mi < 4; mi++) {
                int ar = wm + mi * 16 + grp;          // ar&7 == grp
                const char* rowp = sA + ar * 128 + tg * 4;
                uint32_t a[4];
                uint32_t o0 = (uint32_t)((c0 ^ (ar & 7)) * 16);
                uint32_t o1 = (uint32_t)((c1 ^ (ar & 7)) * 16);
                a[0] = *(const uint32_t*)(rowp + o0);
                a[1] = *(const uint32_t*)(rowp + o0 + 8 * 128);
                a[2] = *(const uint32_t*)(rowp + o1);
                a[3] = *(const uint32_t*)(rowp + o1 + 8 * 128);
                #pragma unroll
                for (int ni = 0; ni < 4; ni++)
                    mma_tf32(acc[mi][ni], a, bfr[ni][0], bfr[ni][1]);
            }
        }
        s = (s == NSTAGE - 1) ? 0 : s + 1;
    }

    // ---- epilogue ----
    const int erow = lane >> 2;
    const int ecol = (lane & 3) * 2;
    #pragma unroll
    for (int mi = 0; mi < 4; mi++) {
        #pragma unroll
        for (int ni = 0; ni < 4; ni++) {
            int r0 = m0 + wm + mi * 16 + erow;
            int c0 = n0 + wn + ni * 8 + ecol;
            float* p0 = C + (size_t)r0 * ldc + c0;
            float* p1 = C + (size_t)(r0 + 8) * ldc + c0;
            if (EPI == 0) {
                *(float2*)p0 = make_float2(acc[mi][ni][0], acc[mi][ni][1]);
                *(float2*)p1 = make_float2(acc[mi][ni][2], acc[mi][ni][3]);
            } else {
                atomicAdd(p0,     acc[mi][ni][0]);
                atomicAdd(p0 + 1, acc[mi][ni][1]);
                atomicAdd(p1,     acc[mi][ni][2]);
                atomicAdd(p1 + 1, acc[mi][ni][3]);
            }
        }
    }
}

// ---------------- small helpers ----------------
__global__ void zero_kernel(float* __restrict__ p, int n) {
    int i = blockIdx.x * blockDim.x + threadIdx.x;
    if (i < n) p[i] = 0.0f;
}

__global__ void precompute_A_kernel(const float* __restrict__ A_log) {
    int i = blockIdx.x * blockDim.x + threadIdx.x;
    if (i < DINNER * DSTATE) g_A[i] = -expf(A_log[i]);
}

// round fp32 -> tf32 (RN, unbiased), float4-vectorized
__global__ void round_tf32_kernel(const float4* __restrict__ in,
                                  uint4* __restrict__ out, int n4) {
    int i = blockIdx.x * blockDim.x + threadIdx.x;
    if (i >= n4) return;
    float4 v = in[i];
    uint4 r;
    r.x = f2tf32(v.x); r.y = f2tf32(v.y);
    r.z = f2tf32(v.z); r.w = f2tf32(v.w);
    out[i] = r;
}

// ---------------- fp32 tiled SGEMM (small GEMMs) ----------------
template<int BM, int BN, int BK, int TM, int TN, int EPI>
__global__ void __launch_bounds__((BM/TM)*(BN/TN))
sgemm_nt(const float* __restrict__ A, int lda,
         const float* __restrict__ Bm, int ldb,
         float* __restrict__ C, int ldc,
         int M, int N, int K, int kChunk,
         const float* __restrict__ bias)
{
    constexpr int THREADS = (BM/TM)*(BN/TN);
    constexpr int KQ = BK / 4;
    constexpr int A4 = BM * BK / 4;
    constexpr int B4 = BN * BK / 4;

    __shared__ float As[BK][BM];
    __shared__ float Bs[BK][BN];

    const int tid = threadIdx.x;
    const int n0  = blockIdx.x * BN;
    const int m0  = blockIdx.y * BM;
    const int kb  = blockIdx.z * kChunk;
    const int ke  = (kb + kChunk < K) ? (kb + kChunk) : K;

    const int tc = tid % (BN / TN);
    const int tr = tid / (BN / TN);

    float acc[TM][TN];
    #pragma unroll
    for (int i = 0; i < TM; i++)
        #pragma unroll
        for (int j = 0; j < TN; j++) acc[i][j] = 0.0f;

    for (int k0 = kb; k0 < ke; k0 += BK) {
        #pragma unroll
        for (int i = tid; i < A4; i += THREADS) {
            int m  = i / KQ;
            int kq = i % KQ;
            float4 v = *(const float4*)&A[(size_t)(m0 + m) * lda + k0 + kq * 4];
            As[kq*4+0][m] = v.x; As[kq*4+1][m] = v.y;
            As[kq*4+2][m] = v.z; As[kq*4+3][m] = v.w;
        }
        #pragma unroll
        for (int i = tid; i < B4; i += THREADS) {
            int n  = i / KQ;
            int kq = i % KQ;
            float4 v = *(const float4*)&Bm[(size_t)(n0 + n) * ldb + k0 + kq * 4];
            Bs[kq*4+0][n] = v.x; Bs[kq*4+1][n] = v.y;
            Bs[kq*4+2][n] = v.z; Bs[kq*4+3][n] = v.w;
        }
        __syncthreads();

        #pragma unroll
        for (int kk = 0; kk < BK; kk++) {
            float a[TM], b[TN];
            #pragma unroll
            for (int i = 0; i < TM; i++) a[i] = As[kk][tr*TM + i];
            #pragma unroll
            for (int j = 0; j < TN; j++) b[j] = Bs[kk][tc*TN + j];
            #pragma unroll
            for (int i = 0; i < TM; i++)
                #pragma unroll
                for (int j = 0; j < TN; j++)
                    acc[i][j] = fmaf(a[i], b[j], acc[i][j]);
        }
        __syncthreads();
    }

    #pragma unroll
    for (int i = 0; i < TM; i++) {
        int m = m0 + tr*TM + i;
        #pragma unroll
        for (int j = 0; j < TN; j++) {
            int n = n0 + tc*TN + j;
            float v = acc[i][j];
            if (EPI == 0) {
                C[(size_t)m * ldc + n] = v;
            } else if (EPI == 1) {
                atomicAdd(&C[(size_t)m * ldc + n], v);
            } else {
                float x = v + bias[n];
                float r2 = fmaxf(x, 0.0f) + log1pf(__expf(-fabsf(x)));
                C[(size_t)m * ldc + n] = r2;
            }
        }
    }
}

// ---------------- conv window shift + SiLU ----------------
__global__ void conv_kernel(const float* __restrict__ cs_in,
                            const float* __restrict__ conv_w,
                            const float* __restrict__ conv_b,
                            float* __restrict__ cs_out)
{
    int idx = blockIdx.x * blockDim.x + threadIdx.x;
    int b = idx >> 13;
    int d = idx & (DINNER - 1);
    float4 cs = ((const float4*)cs_in)[idx];
    float4 w  = ((const float4*)conv_w)[d];
    float xi  = g_xz[(size_t)b * (2*DINNER) + d];
    float s = cs.y*w.x + cs.z*w.y + cs.w*w.z + xi*w.w + conv_b[d];
    float sig = 1.0f / (1.0f + __expf(-s));
    g_xc[idx] = s * sig;
    ((float4*)cs_out)[idx] = make_float4(cs.y, cs.z, cs.w, xi);
}

// ---------------- SSM state update + y (emits y rounded to tf32) ------------
__global__ void ssm_kernel(const float* __restrict__ ssm_in,
                           const float* __restrict__ D_param,
                           float* __restrict__ ssm_out)
{
    __shared__ float bm[DSTATE], cm[DSTATE];
    const int b = blockIdx.y;
    const int d = blockIdx.x * blockDim.x + threadIdx.x;
    if (threadIdx.x < 2*DSTATE) {
        float v = g_xdb[b * XPN + DTRANK + threadIdx.x];
        if (threadIdx.x < DSTATE) bm[threadIdx.x] = v;
        else                      cm[threadIdx.x - DSTATE] = v;
    }
    __syncthreads();

    const int bd = b * DINNER + d;
    const float dtv = g_dt[bd];
    const float xcv = g_xc[bd];
    const float xdt = xcv * dtv;
    const size_t base = (size_t)bd * DSTATE;

    float yacc = 0.0f;
    #pragma unroll
    for (int n = 0; n < DSTATE; n += 4) {
        float4 a  = *(const float4*)&g_A[d * DSTATE + n];
        float4 st = *(const float4*)&ssm_in[base + n];
        float4 ns;
        ns.x = st.x * __expf(a.x * dtv) + xdt * bm[n+0];
        ns.y = st.y * __expf(a.y * dtv) + xdt * bm[n+1];
        ns.z = st.z * __expf(a.z * dtv) + xdt * bm[n+2];
        ns.w = st.w * __expf(a.w * dtv) + xdt * bm[n+3];
        yacc += ns.x * cm[n+0] + ns.y * cm[n+1] + ns.z * cm[n+2] + ns.w * cm[n+3];
        *(float4*)&ssm_out[base + n] = ns;
    }
    yacc += D_param[d] * xcv;
    float zv = g_xz[(size_t)b * (2*DINNER) + DINNER + d];
    yacc *= zv / (1.0f + __expf(-zv));

    g_y[bd] = __uint_as_float(f2tf32(yacc));
}

// ---------------- launch ----------------
extern "C" void kernel_launch(void* const* d_in, const int* in_sizes, int n_in,
                              void* d_out, int out_size)
{
    const float* x       = (const float*)d_in[0];
    const float* cs_in   = (const float*)d_in[1];
    const float* ssm_in  = (const float*)d_in[2];
    const float* W_in    = (const float*)d_in[3];
    const float* conv_w  = (const float*)d_in[4];
    const float* conv_b  = (const float*)d_in[5];
    const float* W_xproj = (const float*)d_in[6];
    const float* W_dt    = (const float*)d_in[7];
    const float* b_dt    = (const float*)d_in[8];
    const float* A_log   = (const float*)d_in[9];
    const float* D_param = (const float*)d_in[10];
    const float* W_out   = (const float*)d_in[11];

    float* out     = (float*)d_out;
    float* cs_out  = out + (size_t)BB * DMODEL;
    float* ssm_out = cs_out + (size_t)BB * DINNER * 4;

    void *p_xz, *p_xc, *p_xdb, *p_dt, *p_xt, *p_y;
    cudaGetSymbolAddress(&p_xz,  g_xz);
    cudaGetSymbolAddress(&p_xc,  g_xc);
    cudaGetSymbolAddress(&p_xdb, g_xdb);
    cudaGetSymbolAddress(&p_dt,  g_dt);
    cudaGetSymbolAddress(&p_xt,  g_xt);
    cudaGetSymbolAddress(&p_y,   g_y);

    const int HSM = NSTAGE * STG_BYTES;   // 98304 bytes -> 2 CTAs/SM
    cudaFuncSetAttribute(tf32_gemm<0,1>, cudaFuncAttributeMaxDynamicSharedMemorySize, HSM);
    cudaFuncSetAttribute(tf32_gemm<1,8>, cudaFuncAttributeMaxDynamicSharedMemorySize, HSM);

    // launches 0-2, then GEMM1 as the 4th launch (ncu window profiles index 3)
    zero_kernel<<<(BB*XPN + 255)/256, 256>>>((float*)p_xdb, BB*XPN);
    zero_kernel<<<(BB*DMODEL + 255)/256, 256>>>(out, BB*DMODEL);
    round_tf32_kernel<<<(BB*DMODEL/4 + 255)/256, 256>>>(
        (const float4*)x, (uint4*)p_xt, BB*DMODEL/4);

    // GEMM1: xz[256,16384] = x @ W_in^T   (tf32 single-product)
    tf32_gemm<0,1><<<dim3((2*DINNER)/GBN, BB/GBM, 1), 256, HSM>>>(
        (const float*)p_xt, W_in, (float*)p_xz, 2*DINNER, DMODEL);

    precompute_A_kernel<<<(DINNER*DSTATE + 255)/256, 256>>>(A_log);

    // conv + SiLU
    conv_kernel<<<(BB*DINNER)/256, 256>>>(cs_in, conv_w, conv_b, cs_out);

    // GEMM3: x_db[256,160] = xc @ W_xproj^T  (fp32, BK=32, split-K=16, atomic)
    sgemm_nt<64,32,32,4,4,1><<<dim3(XPN/32, BB/64, 16), 128>>>(
        (const float*)p_xc, DINNER, W_xproj, DINNER, (float*)p_xdb, XPN,
        BB, XPN, DINNER, DINNER/16, nullptr);

    // GEMM4: dt[256,8192] = softplus(x_db[:, :128] @ W_dt^T + b_dt)  (fp32, BK=32)
    sgemm_nt<64,64,32,4,4,2><<<dim3(DINNER/64, BB/64, 1), 256>>>(
        (const float*)p_xdb, XPN, W_dt, DTRANK, (float*)p_dt, DINNER,
        BB, DINNER, DTRANK, DTRANK, b_dt);

    // SSM update + y (emits y tf32-rounded)
    ssm_kernel<<<dim3(DINNER/256, BB), 256>>>(ssm_in, D_param, ssm_out);

    // GEMM6: out[256,2048] = y @ W_out^T  (tf32, split-K=8 -> 256 CTAs, atomic)
    tf32_gemm<1,8><<<dim3(DMODEL/GBN, BB/GBM, 8), 256, HSM>>>(
        (const float*)p_y, W_out, out, DMODEL, DINNER);
}

// round 15
// speedup vs baseline: 1.2894x; 1.0005x over previous
#include <cuda_runtime.h>
#include <cuda_bf16.h>
#include <math.h>
#include <cstdint>

// ---------------- problem constants ----------------
#define BB       256
#define DMODEL   2048
#define DINNER   8192
#define DSTATE   16
#define DTRANK   128
#define XPN      (DTRANK + 2*DSTATE)   // 160
#define SPLIT6   8

// ---------------- scratch (device globals; no allocation) ----------------
__device__ float g_xz [BB * 2 * DINNER];   // xi | z
__device__ float g_xc [BB * DINNER];
__device__ float g_xdb[BB * XPN];
__device__ float g_dt [BB * DINNER];
__device__ float g_A  [DINNER * DSTATE];
__device__ float g_xt [BB * DMODEL];       // x rounded to tf32
__device__ float g_y  [BB * DINNER];       // y rounded to tf32
__device__ float g_part[SPLIT6 * BB * DMODEL];  // GEMM6 split-K partials

// ---------------- helpers ----------------
__device__ __forceinline__ uint32_t smem_u32(const void* p) {
    uint32_t a;
    asm("{ .reg .u64 t; cvta.to.shared.u64 t, %1; cvt.u32.u64 %0, t; }" : "=r"(a) : "l"(p));
    return a;
}

__device__ __forceinline__ uint32_t f2tf32(float f) {
    uint32_t r;
    asm("cvt.rna.tf32.f32 %0, %1;" : "=r"(r) : "f"(f));
    return r;
}

__device__ __forceinline__ void mma_tf32(float* d, const uint32_t* a,
                                         uint32_t b0, uint32_t b1) {
    asm volatile(
        "mma.sync.aligned.m16n8k8.row.col.f32.tf32.tf32.f32 "
        "{%0,%1,%2,%3}, {%4,%5,%6,%7}, {%8,%9}, {%0,%1,%2,%3};"
        : "+f"(d[0]), "+f"(d[1]), "+f"(d[2]), "+f"(d[3])
        : "r"(a[0]), "r"(a[1]), "r"(a[2]), "r"(a[3]), "r"(b0), "r"(b1));
}

__device__ __forceinline__ void cp16(uint32_t s, const void* g) {
    asm volatile("cp.async.cg.shared.global [%0], [%1], 16;" :: "r"(s), "l"(g));
}
#define CP_COMMIT() asm volatile("cp.async.commit_group;" ::: "memory")
#define CP_WAIT(n)  asm volatile("cp.async.wait_group %0;" :: "n"(n) : "memory")

// ---------------- TF32 single-product GEMM ----------------
// C[M,N] (+)= A[M,K] * B[N,K]^T.  A pre-rounded to tf32 (fp32 storage);
// B raw fp32, cvt.rna at fragment load. m16n8k8 tf32 MMA.
// 256 threads, tile 128x128x32, 3-stage cp.async -> 96 KB, 2 CTAs/SM.
// Single __syncthreads per iter. Swizzle: chunk' = chunk ^ (row & 7).
// EPI: 0 = store to C; 2 = store to C + blockIdx.z * partStride (split-K
// partials, no atomics). iters must be >= 3.
#define GBM 128
#define GBN 128
#define GBK 32
#define A_OFF 0
#define B_OFF 16384
#define STG_BYTES 32768
#define NSTAGE 3

template<int EPI, int SPLITK>
__global__ void __launch_bounds__(256, 2)
tf32_gemm(const float* __restrict__ Af, const float* __restrict__ Bf,
          float* __restrict__ C, int ldc, int K, size_t partStride)
{
    extern __shared__ char smraw[];

    const int tid = threadIdx.x;
    const int n0  = blockIdx.x * GBN;
    const int m0  = blockIdx.y * GBM;
    const int kChunk = K / SPLITK;
    const int kb  = blockIdx.z * kChunk;
    const int iters = kChunk / GBK;

    const uint32_t usm = smem_u32(smraw);

    auto issue = [&](uint32_t sbase, int koff) {
        #pragma unroll
        for (int u = 0; u < 4; u++) {
            int idx = u * 256 + tid;
            int r   = idx >> 3;
            int c   = idx & 7;
            uint32_t so = (uint32_t)(r * 128 + ((c ^ (r & 7)) * 16));
            cp16(sbase + A_OFF + so, Af + (size_t)(m0 + r) * K + koff + c * 4);
            cp16(sbase + B_OFF + so, Bf + (size_t)(n0 + r) * K + koff + c * 4);
        }
    };

    // prologue: 2 stages in flight
    issue(usm, kb);                   CP_COMMIT();
    issue(usm + STG_BYTES, kb + GBK); CP_COMMIT();

    // warp mapping: 2m x 4n, warp tile 64x32
    const int w    = tid >> 5;
    const int lane = tid & 31;
    const int wm   = (w & 1) * 64;
    const int wn   = (w >> 1) * 32;
    const int grp  = lane >> 2;       // 0..7
    const int tg   = lane & 3;        // 0..3

    float acc[4][4][4];
    #pragma unroll
    for (int i = 0; i < 4; i++)
        #pragma unroll
        for (int j = 0; j < 4; j++)
            #pragma unroll
            for (int c = 0; c < 4; c++) acc[i][j][c] = 0.0f;

    int s = 0;
    for (int it = 0; it < iters; ++it) {
        CP_WAIT(1);              // stage s resident
        __syncthreads();         // + all warps done reading stage (it-1)

        if (it + 2 < iters) {
            int s2 = s + 2; if (s2 >= NSTAGE) s2 -= NSTAGE;
            issue(usm + (uint32_t)s2 * STG_BYTES, kb + (it + 2) * GBK);
        }
        CP_COMMIT();

        const char* stg = smraw + (uint32_t)s * STG_BYTES;
        const char* sA  = stg + A_OFF;
        const char* sB  = stg + B_OFF;

        #pragma unroll
        for (int ks = 0; ks < 4; ks++) {
            const int c0 = ks * 2;       // chunk of k = ks*8 + [0..3]
            const int c1 = ks * 2 + 1;   // chunk of k = ks*8 + [4..7]

            // ---- B fragments (4 n8 tiles), cvt.rna to tf32 ----
            uint32_t bfr[4][2];
            #pragma unroll
            for (int ni = 0; ni < 4; ni++) {
                int br = wn + ni * 8 + grp;
                const char* rowp = sB + br * 128 + tg * 4;
                float v0 = *(const float*)(rowp + ((c0 ^ (br & 7)) * 16));
                float v1 = *(const float*)(rowp + ((c1 ^ (br & 7)) * 16));
                bfr[ni][0] = f2tf32(v0);
                bfr[ni][1] = f2tf32(v1);
            }
            // ---- A fragments (pre-rounded) + MMAs ----
            #pragma unroll
            for (int mi = 0; mi < 4; mi++) {
                int ar = wm + mi * 16 + grp;
                const char* rowp = sA + ar * 128 + tg * 4;
                uint32_t a[4];
                uint32_t o0 = (uint32_t)((c0 ^ (ar & 7)) * 16);
                uint32_t o1 = (uint32_t)((c1 ^ (ar & 7)) * 16);
                a[0] = *(const uint32_t*)(rowp + o0);
                a[1] = *(const uint32_t*)(rowp + o0 + 8 * 128);
                a[2] = *(const uint32_t*)(rowp + o1);
                a[3] = *(const uint32_t*)(rowp + o1 + 8 * 128);
                #pragma unroll
                for (int ni = 0; ni < 4; ni++)
                    mma_tf32(acc[mi][ni], a, bfr[ni][0], bfr[ni][1]);
            }
        }
        s = (s == NSTAGE - 1) ? 0 : s + 1;
    }

    // ---- epilogue ----
    float* Cb = (EPI == 2) ? (C + (size_t)blockIdx.z * partStride) : C;
    const int erow = lane >> 2;
    const int ecol = (lane & 3) * 2;
    #pragma unroll
    for (int mi = 0; mi < 4; mi++) {
        #pragma unroll
        for (int ni = 0; ni < 4; ni++) {
            int r0 = m0 + wm + mi * 16 + erow;
            int c0 = n0 + wn + ni * 8 + ecol;
            float* p0 = Cb + (size_t)r0 * ldc + c0;
            float* p1 = Cb + (size_t)(r0 + 8) * ldc + c0;
            *(float2*)p0 = make_float2(acc[mi][ni][0], acc[mi][ni][1]);
            *(float2*)p1 = make_float2(acc[mi][ni][2], acc[mi][ni][3]);
        }
    }
}

// ---------------- reduce split-K partials: out = sum_s part[s] ----------------
__global__ void reduce_part_kernel(const float4* __restrict__ part,
                                   float4* __restrict__ out, int n4) {
    int i = blockIdx.x * blockDim.x + threadIdx.x;
    if (i >= n4) return;
    float4 a = part[i];
    #pragma unroll
    for (int s2 = 1; s2 < SPLIT6; s2++) {
        float4 b = part[(size_t)s2 * n4 + i];
        a.x += b.x; a.y += b.y; a.z += b.z; a.w += b.w;
    }
    out[i] = a;
}

// ---------------- small helpers ----------------
__global__ void zero_kernel(float* __restrict__ p, int n) {
    int i = blockIdx.x * blockDim.x + threadIdx.x;
    if (i < n) p[i] = 0.0f;
}

__global__ void precompute_A_kernel(const float* __restrict__ A_log) {
    int i = blockIdx.x * blockDim.x + threadIdx.x;
    if (i < DINNER * DSTATE) g_A[i] = -expf(A_log[i]);
}

// round fp32 -> tf32 (RN, unbiased), float4-vectorized
__global__ void round_tf32_kernel(const float4* __restrict__ in,
                                  uint4* __restrict__ out, int n4) {
    int i = blockIdx.x * blockDim.x + threadIdx.x;
    if (i >= n4) return;
    float4 v = in[i];
    uint4 r;
    r.x = f2tf32(v.x); r.y = f2tf32(v.y);
    r.z = f2tf32(v.z); r.w = f2tf32(v.w);
    out[i] = r;
}

// ---------------- fp32 tiled SGEMM (small GEMMs) ----------------
template<int BM, int BN, int BK, int TM, int TN, int EPI>
__global__ void __launch_bounds__((BM/TM)*(BN/TN))
sgemm_nt(const float* __restrict__ A, int lda,
         const float* __restrict__ Bm, int ldb,
         float* __restrict__ C, int ldc,
         int M, int N, int K, int kChunk,
         const float* __restrict__ bias)
{
    constexpr int THREADS = (BM/TM)*(BN/TN);
    constexpr int KQ = BK / 4;
    constexpr int A4 = BM * BK / 4;
    constexpr int B4 = BN * BK / 4;

    __shared__ float As[BK][BM];
    __shared__ float Bs[BK][BN];

    const int tid = threadIdx.x;
    const int n0  = blockIdx.x * BN;
    const int m0  = blockIdx.y * BM;
    const int kb  = blockIdx.z * kChunk;
    const int ke  = (kb + kChunk < K) ? (kb + kChunk) : K;

    const int tc = tid % (BN / TN);
    const int tr = tid / (BN / TN);

    float acc[TM][TN];
    #pragma unroll
    for (int i = 0; i < TM; i++)
        #pragma unroll
        for (int j = 0; j < TN; j++) acc[i][j] = 0.0f;

    for (int k0 = kb; k0 < ke; k0 += BK) {
        #pragma unroll
        for (int i = tid; i < A4; i += THREADS) {
            int m  = i / KQ;
            int kq = i % KQ;
            float4 v = *(const float4*)&A[(size_t)(m0 + m) * lda + k0 + kq * 4];
            As[kq*4+0][m] = v.x; As[kq*4+1][m] = v.y;
            As[kq*4+2][m] = v.z; As[kq*4+3][m] = v.w;
        }
        #pragma unroll
        for (int i = tid; i < B4; i += THREADS) {
            int n  = i / KQ;
            int kq = i % KQ;
            float4 v = *(const float4*)&Bm[(size_t)(n0 + n) * ldb + k0 + kq * 4];
            Bs[kq*4+0][n] = v.x; Bs[kq*4+1][n] = v.y;
            Bs[kq*4+2][n] = v.z; Bs[kq*4+3][n] = v.w;
        }
        __syncthreads();

        #pragma unroll
        for (int kk = 0; kk < BK; kk++) {
            float a[TM], b[TN];
            #pragma unroll
            for (int i = 0; i < TM; i++) a[i] = As[kk][tr*TM + i];
            #pragma unroll
            for (int j = 0; j < TN; j++) b[j] = Bs[kk][tc*TN + j];
            #pragma unroll
            for (int i = 0; i < TM; i++)
                #pragma unroll
                for (int j = 0; j < TN; j++)
                    acc[i][j] = fmaf(a[i], b[j], acc[i][j]);
        }
        __syncthreads();
    }

    #pragma unroll
    for (int i = 0; i < TM; i++) {
        int m = m0 + tr*TM + i;
        #pragma unroll
        for (int j = 0; j < TN; j++) {
            int n = n0 + tc*TN + j;
            float v = acc[i][j];
            if (EPI == 0) {
                C[(size_t)m * ldc + n] = v;
            } else if (EPI == 1) {
                atomicAdd(&C[(size_t)m * ldc + n], v);
            } else {
                float x = v + bias[n];
                float r2 = fmaxf(x, 0.0f) + log1pf(__expf(-fabsf(x)));
                C[(size_t)m * ldc + n] = r2;
            }
        }
    }
}

// ---------------- conv window shift + SiLU ----------------
__global__ void conv_kernel(const float* __restrict__ cs_in,
                            const float* __restrict__ conv_w,
                            const float* __restrict__ conv_b,
                            float* __restrict__ cs_out)
{
    int idx = blockIdx.x * blockDim.x + threadIdx.x;
    int b = idx >> 13;
    int d = idx & (DINNER - 1);
    float4 cs = ((const float4*)cs_in)[idx];
    float4 w  = ((const float4*)conv_w)[d];
    float xi  = g_xz[(size_t)b * (2*DINNER) + d];
    float s = cs.y*w.x + cs.z*w.y + cs.w*w.z + xi*w.w + conv_b[d];
    float sig = 1.0f / (1.0f + __expf(-s));
    g_xc[idx] = s * sig;
    ((float4*)cs_out)[idx] = make_float4(cs.y, cs.z, cs.w, xi);
}

// ---------------- SSM state update + y (emits y rounded to tf32) ------------
__global__ void ssm_kernel(const float* __restrict__ ssm_in,
                           const float* __restrict__ D_param,
                           float* __restrict__ ssm_out)
{
    __shared__ float bm[DSTATE], cm[DSTATE];
    const int b = blockIdx.y;
    const int d = blockIdx.x * blockDim.x + threadIdx.x;
    if (threadIdx.x < 2*DSTATE) {
        float v = g_xdb[b * XPN + DTRANK + threadIdx.x];
        if (threadIdx.x < DSTATE) bm[threadIdx.x] = v;
        else                      cm[threadIdx.x - DSTATE] = v;
    }
    __syncthreads();

    const int bd = b * DINNER + d;
    const float dtv = g_dt[bd];
    const float xcv = g_xc[bd];
    const float xdt = xcv * dtv;
    const size_t base = (size_t)bd * DSTATE;

    float yacc = 0.0f;
    #pragma unroll
    for (int n = 0; n < DSTATE; n += 4) {
        float4 a  = *(const float4*)&g_A[d * DSTATE + n];
        float4 st = *(const float4*)&ssm_in[base + n];
        float4 ns;
        ns.x = st.x * __expf(a.x * dtv) + xdt * bm[n+0];
        ns.y = st.y * __expf(a.y * dtv) + xdt * bm[n+1];
        ns.z = st.z * __expf(a.z * dtv) + xdt * bm[n+2];
        ns.w = st.w * __expf(a.w * dtv) + xdt * bm[n+3];
        yacc += ns.x * cm[n+0] + ns.y * cm[n+1] + ns.z * cm[n+2] + ns.w * cm[n+3];
        *(float4*)&ssm_out[base + n] = ns;
    }
    yacc += D_param[d] * xcv;
    float zv = g_xz[(size_t)b * (2*DINNER) + DINNER + d];
    yacc *= zv / (1.0f + __expf(-zv));

    g_y[bd] = __uint_as_float(f2tf32(yacc));
}

// ---------------- launch ----------------
extern "C" void kernel_launch(void* const* d_in, const int* in_sizes, int n_in,
                              void* d_out, int out_size)
{
    const float* x       = (const float*)d_in[0];
    const float* cs_in   = (const float*)d_in[1];
    const float* ssm_in  = (const float*)d_in[2];
    const float* W_in    = (const float*)d_in[3];
    const float* conv_w  = (const float*)d_in[4];
    const float* conv_b  = (const float*)d_in[5];
    const float* W_xproj = (const float*)d_in[6];
    const float* W_dt    = (const float*)d_in[7];
    const float* b_dt    = (const float*)d_in[8];
    const float* A_log   = (const float*)d_in[9];
    const float* D_param = (const float*)d_in[10];
    const float* W_out   = (const float*)d_in[11];

    float* out     = (float*)d_out;
    float* cs_out  = out + (size_t)BB * DMODEL;
    float* ssm_out = cs_out + (size_t)BB * DINNER * 4;

    void *p_xz, *p_xc, *p_xdb, *p_dt, *p_xt, *p_y, *p_part;
    cudaGetSymbolAddress(&p_xz,  g_xz);
    cudaGetSymbolAddress(&p_xc,  g_xc);
    cudaGetSymbolAddress(&p_xdb, g_xdb);
    cudaGetSymbolAddress(&p_dt,  g_dt);
    cudaGetSymbolAddress(&p_xt,  g_xt);
    cudaGetSymbolAddress(&p_y,   g_y);
    cudaGetSymbolAddress(&p_part, g_part);

    const int HSM = NSTAGE * STG_BYTES;   // 98304 bytes -> 2 CTAs/SM
    cudaFuncSetAttribute(tf32_gemm<0,1>, cudaFuncAttributeMaxDynamicSharedMemorySize, HSM);
    cudaFuncSetAttribute(tf32_gemm<2,SPLIT6>, cudaFuncAttributeMaxDynamicSharedMemorySize, HSM);

    // launches 0-2, then GEMM1 as the 4th launch (ncu window profiles index 3)
    zero_kernel<<<(BB*XPN + 255)/256, 256>>>((float*)p_xdb, BB*XPN);
    precompute_A_kernel<<<(DINNER*DSTATE + 255)/256, 256>>>(A_log);
    round_tf32_kernel<<<(BB*DMODEL/4 + 255)/256, 256>>>(
        (const float4*)x, (uint4*)p_xt, BB*DMODEL/4);

    // GEMM1: xz[256,16384] = x @ W_in^T   (tf32 single-product)
    tf32_gemm<0,1><<<dim3((2*DINNER)/GBN, BB/GBM, 1), 256, HSM>>>(
        (const float*)p_xt, W_in, (float*)p_xz, 2*DINNER, DMODEL, 0);

    // conv + SiLU
    conv_kernel<<<(BB*DINNER)/256, 256>>>(cs_in, conv_w, conv_b, cs_out);

    // GEMM3: x_db[256,160] = xc @ W_xproj^T  (fp32, BK=32, split-K=16, atomic)
    sgemm_nt<64,32,32,4,4,1><<<dim3(XPN/32, BB/64, 16), 128>>>(
        (const float*)p_xc, DINNER, W_xproj, DINNER, (float*)p_xdb, XPN,
        BB, XPN, DINNER, DINNER/16, nullptr);

    // GEMM4: dt[256,8192] = softplus(x_db[:, :128] @ W_dt^T + b_dt)  (fp32, BK=32)
    sgemm_nt<64,64,32,4,4,2><<<dim3(DINNER/64, BB/64, 1), 256>>>(
        (const float*)p_xdb, XPN, W_dt, DTRANK, (float*)p_dt, DINNER,
        BB, DINNER, DTRANK, DTRANK, b_dt);

    // SSM update + y (emits y tf32-rounded)
    ssm_kernel<<<dim3(DINNER/256, BB), 256>>>(ssm_in, D_param, ssm_out);

    // GEMM6: split-K partials (no atomics), then reduce
    tf32_gemm<2,SPLIT6><<<dim3(DMODEL/GBN, BB/GBM, SPLIT6), 256, HSM>>>(
        (const float*)p_y, W_out, (float*)p_part, DMODEL, DINNER,
        (size_t)BB * DMODEL);
    reduce_part_kernel<<<(BB*DMODEL/4 + 255)/256, 256>>>(
        (const float4*)p_part, (float4*)out, BB*DMODEL/4);
}

// round 16
// speedup vs baseline: 1.4365x; 1.1141x over previous
#include <cuda_runtime.h>
#include <math.h>
#include <cstdint>

// ---------------- problem constants ----------------
#define BB       256
#define DMODEL   2048
#define DINNER   8192
#define DSTATE   16
#define DTRANK   128
#define XPN      (DTRANK + 2*DSTATE)   // 160
#define SPLIT6   8
#define SPLIT3   32

// ---------------- scratch (device globals; no allocation) ----------------
__device__ float g_xz  [BB * 2 * DINNER];     // xi | z (plain)
__device__ float g_xc  [BB * DINNER];         // xc, tf32-rounded, k-permuted
__device__ float g_xdb [BB * XPN];            // x_db plain (Bm/Cm for ssm)
__device__ float g_dtin[BB * DTRANK];         // x_db[:, :128] tf32, permuted
__device__ float g_dt  [BB * DINNER];         // softplus(dt) plain
__device__ float g_A   [DINNER * DSTATE];
__device__ float g_xt  [BB * DMODEL];         // x tf32, permuted
__device__ float g_y   [BB * DINNER];         // y tf32, permuted
__device__ float g_part [SPLIT6 * BB * DMODEL];  // GEMM6 partials
__device__ float g_part3[SPLIT3 * BB * XPN];     // GEMM3 partials

// ---------------- helpers ----------------
__device__ __forceinline__ uint32_t smem_u32(const void* p) {
    uint32_t a;
    asm("{ .reg .u64 t; cvta.to.shared.u64 t, %1; cvt.u32.u64 %0, t; }" : "=r"(a) : "l"(p));
    return a;
}

__device__ __forceinline__ uint32_t f2tf32(float f) {
    uint32_t r;
    asm("cvt.rna.tf32.f32 %0, %1;" : "=r"(r) : "f"(f));
    return r;
}

__device__ __forceinline__ void mma_tf32(float* d, const uint32_t* a,
                                         uint32_t b0, uint32_t b1) {
    asm volatile(
        "mma.sync.aligned.m16n8k8.row.col.f32.tf32.tf32.f32 "
        "{%0,%1,%2,%3}, {%4,%5,%6,%7}, {%8,%9}, {%0,%1,%2,%3};"
        : "+f"(d[0]), "+f"(d[1]), "+f"(d[2]), "+f"(d[3])
        : "r"(a[0]), "r"(a[1]), "r"(a[2]), "r"(a[3]), "r"(b0), "r"(b1));
}

__device__ __forceinline__ void cp16(uint32_t s, const void* g) {
    asm volatile("cp.async.cg.shared.global [%0], [%1], 16;" :: "r"(s), "l"(g));
}
#define CP_COMMIT() asm volatile("cp.async.commit_group;" ::: "memory")
#define CP_WAIT(n)  asm volatile("cp.async.wait_group %0;" :: "n"(n) : "memory")

// k-permutation within each 8-group: storage order (0,4,1,5,2,6,3,7)
// pos(j) = ((j&3)<<1) | (j>>2)
__device__ __forceinline__ int kperm(int j) { return ((j & 3) << 1) | (j >> 2); }

// ---------------- TF32 single-product GEMM ----------------
// C[M,N] (+)= A[M,K] * B[N,K]^T.
// A: tf32-rounded fp32, K-PERMUTED per 8-group (pairs (k,k+4) adjacent ->
//    one LDS.64 per fragment pair). B: raw fp32, cvt.rna at fragment load.
// 256 threads, tile 128x128x32, 3-stage cp.async (96 KB, 2 CTAs/SM),
// single __syncthreads per iter. B smem: chunk swizzle c^(r&7); A same.
// B rows clamped to nlim-1 (partial-N); epilogue stores guarded c0 < nlim.
// EPI: 0 = store; 2 = store partials at C + z*partStride; 3 = softplus(+bias).
// iters must be >= 3 (K/SPLITK/32 >= 3) except small-K where >= 2 works via
// the same schedule (prologue fills 2 stages).
#define GBM 128
#define GBN 128
#define GBK 32
#define A_OFF 0
#define B_OFF 16384
#define STG_BYTES 32768
#define NSTAGE 3

template<int EPI, int SPLITK>
__global__ void __launch_bounds__(256, 2)
tf32_gemm(const float* __restrict__ Af, int lda,
          const float* __restrict__ Bf, int ldb,
          float* __restrict__ C, int ldc, int K, int nlim,
          size_t partStride, const float* __restrict__ bias)
{
    extern __shared__ char smraw[];

    const int tid = threadIdx.x;
    const int n0  = blockIdx.x * GBN;
    const int m0  = blockIdx.y * GBM;
    const int kChunk = K / SPLITK;
    const int kb  = blockIdx.z * kChunk;
    const int iters = kChunk / GBK;

    const uint32_t usm = smem_u32(smraw);

    auto issue = [&](uint32_t sbase, int koff) {
        #pragma unroll
        for (int u = 0; u < 4; u++) {
            int idx = u * 256 + tid;
            int r   = idx >> 3;
            int c   = idx & 7;
            uint32_t so = (uint32_t)(r * 128 + ((c ^ (r & 7)) * 16));
            cp16(sbase + A_OFF + so, Af + (size_t)(m0 + r) * lda + koff + c * 4);
            int rB = n0 + r; if (rB >= nlim) rB = nlim - 1;
            cp16(sbase + B_OFF + so, Bf + (size_t)rB * ldb + koff + c * 4);
        }
    };

    // prologue: 2 stages in flight
    issue(usm, kb);                   CP_COMMIT();
    issue(usm + STG_BYTES, kb + GBK); CP_COMMIT();

    // warp mapping: 2m x 4n, warp tile 64x32
    const int w    = tid >> 5;
    const int lane = tid & 31;
    const int wm   = (w & 1) * 64;
    const int wn   = (w >> 1) * 32;
    const int grp  = lane >> 2;       // 0..7
    const int tg   = lane & 3;        // 0..3

    float acc[4][4][4];
    #pragma unroll
    for (int i = 0; i < 4; i++)
        #pragma unroll
        for (int j = 0; j < 4; j++)
            #pragma unroll
            for (int c = 0; c < 4; c++) acc[i][j][c] = 0.0f;

    int s = 0;
    for (int it = 0; it < iters; ++it) {
        CP_WAIT(1);
        __syncthreads();

        if (it + 2 < iters) {
            int s2 = s + 2; if (s2 >= NSTAGE) s2 -= NSTAGE;
            issue(usm + (uint32_t)s2 * STG_BYTES, kb + (it + 2) * GBK);
        }
        CP_COMMIT();

        const char* stg = smraw + (uint32_t)s * STG_BYTES;
        const char* sA  = stg + A_OFF;
        const char* sB  = stg + B_OFF;

        #pragma unroll
        for (int ks = 0; ks < 4; ks++) {
            const int c0 = ks * 2;
            const int c1 = ks * 2 + 1;
            const int cA = ks * 2 + (tg >> 1);        // A permuted chunk
            const uint32_t aoff = (uint32_t)((tg & 1) * 8);

            // ---- B fragments (plain layout): k=tg and k=tg+4 ----
            uint32_t bfr[4][2];
            #pragma unroll
            for (int ni = 0; ni < 4; ni++) {
                int br = wn + ni * 8 + grp;
                const char* rowp = sB + br * 128 + tg * 4;
                float v0 = *(const float*)(rowp + ((c0 ^ (br & 7)) * 16));
                float v1 = *(const float*)(rowp + ((c1 ^ (br & 7)) * 16));
                bfr[ni][0] = f2tf32(v0);
                bfr[ni][1] = f2tf32(v1);
            }
            // ---- A fragments: permuted pairs via LDS.64 ----
            #pragma unroll
            for (int mi = 0; mi < 4; mi++) {
                int ar0 = wm + mi * 16 + grp;
                int ar1 = ar0 + 8;
                uint2 v0 = *(const uint2*)(sA + ar0 * 128 +
                             ((cA ^ (ar0 & 7)) * 16) + aoff);
                uint2 v1 = *(const uint2*)(sA + ar1 * 128 +
                             ((cA ^ (ar1 & 7)) * 16) + aoff);
                uint32_t a[4] = { v0.x, v1.x, v0.y, v1.y };
                #pragma unroll
                for (int ni = 0; ni < 4; ni++)
                    mma_tf32(acc[mi][ni], a, bfr[ni][0], bfr[ni][1]);
            }
        }
        s = (s == NSTAGE - 1) ? 0 : s + 1;
    }

    // ---- epilogue ----
    float* Cb = (EPI == 2) ? (C + (size_t)blockIdx.z * partStride) : C;
    const int erow = lane >> 2;
    const int ecol = (lane & 3) * 2;
    #pragma unroll
    for (int mi = 0; mi < 4; mi++) {
        #pragma unroll
        for (int ni = 0; ni < 4; ni++) {
            int r0 = m0 + wm + mi * 16 + erow;
            int c0 = n0 + wn + ni * 8 + ecol;
            if (c0 >= nlim) continue;
            float* p0 = Cb + (size_t)r0 * ldc + c0;
            float* p1 = Cb + (size_t)(r0 + 8) * ldc + c0;
            if (EPI == 3) {
                float b0 = bias[c0], b1 = bias[c0 + 1];
                float v[4] = { acc[mi][ni][0] + b0, acc[mi][ni][1] + b1,
                               acc[mi][ni][2] + b0, acc[mi][ni][3] + b1 };
                #pragma unroll
                for (int q = 0; q < 4; q++)
                    v[q] = fmaxf(v[q], 0.0f) + log1pf(__expf(-fabsf(v[q])));
                *(float2*)p0 = make_float2(v[0], v[1]);
                *(float2*)p1 = make_float2(v[2], v[3]);
            } else {
                *(float2*)p0 = make_float2(acc[mi][ni][0], acc[mi][ni][1]);
                *(float2*)p1 = make_float2(acc[mi][ni][2], acc[mi][ni][3]);
            }
        }
    }
}

// ---------------- reduces ----------------
__global__ void reduce_part_kernel(const float4* __restrict__ part,
                                   float4* __restrict__ out, int n4) {
    int i = blockIdx.x * blockDim.x + threadIdx.x;
    if (i >= n4) return;
    float4 a = part[i];
    #pragma unroll
    for (int s2 = 1; s2 < SPLIT6; s2++) {
        float4 b = part[(size_t)s2 * n4 + i];
        a.x += b.x; a.y += b.y; a.z += b.z; a.w += b.w;
    }
    out[i] = a;
}

// GEMM3 partials -> x_db (plain) + dt_in (tf32, permuted, first 128 cols)
__global__ void reduce3_kernel() {
    int i = blockIdx.x * blockDim.x + threadIdx.x;
    const int n = BB * XPN;
    if (i >= n) return;
    float s = 0.0f;
    #pragma unroll 4
    for (int s2 = 0; s2 < SPLIT3; s2++) s += g_part3[(size_t)s2 * n + i];
    g_xdb[i] = s;
    int r = i / XPN, c = i - r * XPN;
    if (c < DTRANK)
        g_dtin[r * DTRANK + (c & ~7) + kperm(c & 7)] = __uint_as_float(f2tf32(s));
}

// ---------------- small helpers ----------------
__global__ void precompute_A_kernel(const float* __restrict__ A_log) {
    int i = blockIdx.x * blockDim.x + threadIdx.x;
    if (i < DINNER * DSTATE) g_A[i] = -expf(A_log[i]);
}

// round fp32 -> tf32 AND k-permute per 8-group (one 8-group per thread)
__global__ void round_perm_kernel(const float4* __restrict__ in,
                                  uint4* __restrict__ out, int n8) {
    int i = blockIdx.x * blockDim.x + threadIdx.x;
    if (i >= n8) return;
    float4 lo = in[2 * i];       // k 0..3
    float4 hi = in[2 * i + 1];   // k 4..7
    uint4 o0, o1;
    o0.x = f2tf32(lo.x); o0.y = f2tf32(hi.x);
    o0.z = f2tf32(lo.y); o0.w = f2tf32(hi.y);
    o1.x = f2tf32(lo.z); o1.y = f2tf32(hi.z);
    o1.z = f2tf32(lo.w); o1.w = f2tf32(hi.w);
    out[2 * i]     = o0;
    out[2 * i + 1] = o1;
}

// ---------------- conv window shift + SiLU (xc stored tf32+permuted) --------
__global__ void conv_kernel(const float* __restrict__ cs_in,
                            const float* __restrict__ conv_w,
                            const float* __restrict__ conv_b,
                            float* __restrict__ cs_out)
{
    int idx = blockIdx.x * blockDim.x + threadIdx.x;
    int b = idx >> 13;
    int d = idx & (DINNER - 1);
    float4 cs = ((const float4*)cs_in)[idx];
    float4 w  = ((const float4*)conv_w)[d];
    float xi  = g_xz[(size_t)b * (2*DINNER) + d];
    float s = cs.y*w.x + cs.z*w.y + cs.w*w.z + xi*w.w + conv_b[d];
    float sig = 1.0f / (1.0f + __expf(-s));
    float xc = s * sig;
    g_xc[(idx & ~7) + kperm(d & 7)] = __uint_as_float(f2tf32(xc));
    ((float4*)cs_out)[idx] = make_float4(cs.y, cs.z, cs.w, xi);
}

// ---------------- SSM state update + y (y stored tf32+permuted) -------------
__global__ void ssm_kernel(const float* __restrict__ ssm_in,
                           const float* __restrict__ D_param,
                           float* __restrict__ ssm_out)
{
    __shared__ float bm[DSTATE], cm[DSTATE];
    const int b = blockIdx.y;
    const int d = blockIdx.x * blockDim.x + threadIdx.x;
    if (threadIdx.x < 2*DSTATE) {
        float v = g_xdb[b * XPN + DTRANK + threadIdx.x];
        if (threadIdx.x < DSTATE) bm[threadIdx.x] = v;
        else                      cm[threadIdx.x - DSTATE] = v;
    }
    __syncthreads();

    const int bd = b * DINNER + d;
    const int pp = (bd & ~7) + kperm(d & 7);
    const float dtv = g_dt[bd];
    const float xcv = g_xc[pp];
    const float xdt = xcv * dtv;
    const size_t base = (size_t)bd * DSTATE;

    float yacc = 0.0f;
    #pragma unroll
    for (int n = 0; n < DSTATE; n += 4) {
        float4 a  = *(const float4*)&g_A[d * DSTATE + n];
        float4 st = *(const float4*)&ssm_in[base + n];
        float4 ns;
        ns.x = st.x * __expf(a.x * dtv) + xdt * bm[n+0];
        ns.y = st.y * __expf(a.y * dtv) + xdt * bm[n+1];
        ns.z = st.z * __expf(a.z * dtv) + xdt * bm[n+2];
        ns.w = st.w * __expf(a.w * dtv) + xdt * bm[n+3];
        yacc += ns.x * cm[n+0] + ns.y * cm[n+1] + ns.z * cm[n+2] + ns.w * cm[n+3];
        *(float4*)&ssm_out[base + n] = ns;
    }
    yacc += D_param[d] * xcv;
    float zv = g_xz[(size_t)b * (2*DINNER) + DINNER + d];
    yacc *= zv / (1.0f + __expf(-zv));

    g_y[pp] = __uint_as_float(f2tf32(yacc));
}

// ---------------- launch ----------------
extern "C" void kernel_launch(void* const* d_in, const int* in_sizes, int n_in,
                              void* d_out, int out_size)
{
    const float* x       = (const float*)d_in[0];
    const float* cs_in   = (const float*)d_in[1];
    const float* ssm_in  = (const float*)d_in[2];
    const float* W_in    = (const float*)d_in[3];
    const float* conv_w  = (const float*)d_in[4];
    const float* conv_b  = (const float*)d_in[5];
    const float* W_xproj = (const float*)d_in[6];
    const float* W_dt    = (const float*)d_in[7];
    const float* b_dt    = (const float*)d_in[8];
    const float* A_log   = (const float*)d_in[9];
    const float* D_param = (const float*)d_in[10];
    const float* W_out   = (const float*)d_in[11];

    float* out     = (float*)d_out;
    float* cs_out  = out + (size_t)BB * DMODEL;
    float* ssm_out = cs_out + (size_t)BB * DINNER * 4;

    void *p_xz, *p_xc, *p_dtin, *p_dt, *p_xt, *p_y, *p_part, *p_part3;
    cudaGetSymbolAddress(&p_xz,   g_xz);
    cudaGetSymbolAddress(&p_xc,   g_xc);
    cudaGetSymbolAddress(&p_dtin, g_dtin);
    cudaGetSymbolAddress(&p_dt,   g_dt);
    cudaGetSymbolAddress(&p_xt,   g_xt);
    cudaGetSymbolAddress(&p_y,    g_y);
    cudaGetSymbolAddress(&p_part, g_part);
    cudaGetSymbolAddress(&p_part3, g_part3);

    const int HSM = NSTAGE * STG_BYTES;   // 98304 bytes -> 2 CTAs/SM
    cudaFuncSetAttribute(tf32_gemm<0,1>,      cudaFuncAttributeMaxDynamicSharedMemorySize, HSM);
    cudaFuncSetAttribute(tf32_gemm<2,SPLIT3>, cudaFuncAttributeMaxDynamicSharedMemorySize, HSM);
    cudaFuncSetAttribute(tf32_gemm<3,1>,      cudaFuncAttributeMaxDynamicSharedMemorySize, HSM);
    cudaFuncSetAttribute(tf32_gemm<2,SPLIT6>, cudaFuncAttributeMaxDynamicSharedMemorySize, HSM);

    // 0: A precompute  1: x round+permute  2: GEMM1  3: conv (profiled)
    precompute_A_kernel<<<(DINNER*DSTATE + 255)/256, 256>>>(A_log);
    round_perm_kernel<<<(BB*DMODEL/8 + 255)/256, 256>>>(
        (const float4*)x, (uint4*)p_xt, BB*DMODEL/8);

    // GEMM1: xz[256,16384] = x @ W_in^T
    tf32_gemm<0,1><<<dim3((2*DINNER)/GBN, BB/GBM, 1), 256, HSM>>>(
        (const float*)p_xt, DMODEL, W_in, DMODEL,
        (float*)p_xz, 2*DINNER, DMODEL, 2*DINNER, 0, nullptr);

    // conv + SiLU (writes cs_out + xc tf32/permuted)
    conv_kernel<<<(BB*DINNER)/256, 256>>>(cs_in, conv_w, conv_b, cs_out);

    // GEMM3: x_db partials = xc @ W_xproj^T  (N=160 clamped, split-K=32)
    tf32_gemm<2,SPLIT3><<<dim3(2, BB/GBM, SPLIT3), 256, HSM>>>(
        (const float*)p_xc, DINNER, W_xproj, DINNER,
        (float*)p_part3, XPN, DINNER, XPN, (size_t)BB * XPN, nullptr);
    reduce3_kernel<<<(BB*XPN + 255)/256, 256>>>();

    // GEMM4: dt = softplus(dt_in @ W_dt^T + b_dt)   (K=128)
    tf32_gemm<3,1><<<dim3(DINNER/GBN, BB/GBM, 1), 256, HSM>>>(
        (const float*)p_dtin, DTRANK, W_dt, DTRANK,
        (float*)p_dt, DINNER, DTRANK, DINNER, 0, b_dt);

    // SSM update + y (emits y tf32/permuted)
    ssm_kernel<<<dim3(DINNER/256, BB), 256>>>(ssm_in, D_param, ssm_out);

    // GEMM6: out partials = y @ W_out^T  (split-K=8), then reduce
    tf32_gemm<2,SPLIT6><<<dim3(DMODEL/GBN, BB/GBM, SPLIT6), 256, HSM>>>(
        (const float*)p_y, DINNER, W_out, DINNER,
        (float*)p_part, DMODEL, DINNER, DMODEL, (size_t)BB * DMODEL, nullptr);
    reduce_part_kernel<<<(BB*DMODEL/4 + 255)/256, 256>>>(
        (const float4*)p_part, (float4*)out, BB*DMODEL/4);
}